// round 11
// baseline (speedup 1.0000x reference)
#include <cuda_runtime.h>
#include <cuda_bf16.h>
#include <math.h>

#define NMAX 100000
#define EMAX 1600000
#define H 128
#define C 40
#define SEG 512
#define NB ((NMAX + SEG - 1) / SEG)

typedef unsigned long long ULL;

// ---------------- scratch -------------------------------------------------
__device__ float g_dinv[NMAX];
__device__ int   g_cnt[NMAX];
__device__ int   g_rowstart[NMAX + 1];
__device__ int   g_cursor[NMAX];
__device__ int   g_bagg[NB];
__device__ int   g_bpre[NB];
__device__ int   g_bflag[NB];
__device__ int   g_csr_src[EMAX];
__device__ float g_csr_w[EMAX];
__device__ float g_lin[(size_t)NMAX * H];                 // t = h0 @ W1
__device__ __nv_bfloat16 g_linb[(size_t)NMAX * H];        // bf16 shadow of t
__device__ float g_agg[(size_t)NMAX * H];                 // gx (layer0) then h1
__device__ float g_h0 [(size_t)NMAX * H];

// ---------------- helpers ---------------------------------------------------
__device__ __forceinline__ ULL ffma2(ULL a, ULL b, ULL c) {
    ULL d;
    asm("fma.rn.f32x2 %0, %1, %2, %3;" : "=l"(d) : "l"(a), "l"(b), "l"(c));
    return d;
}
__device__ __forceinline__ ULL fdup(float x) {
    ULL r;
    asm("mov.b64 %0, {%1, %1};" : "=l"(r) : "f"(x));
    return r;
}
__device__ __forceinline__ unsigned cvt_tf32(float f) {
    unsigned u;
    asm("cvt.rna.tf32.f32 %0, %1;" : "=r"(u) : "f"(f));
    return u;
}
__device__ __forceinline__ ULL policy_evict_last() {
    ULL pol;
    asm("createpolicy.fractional.L2::evict_last.b64 %0, 1.0;" : "=l"(pol));
    return pol;
}
__device__ __forceinline__ ULL policy_evict_first() {
    ULL pol;
    asm("createpolicy.fractional.L2::evict_first.b64 %0, 1.0;" : "=l"(pol));
    return pol;
}
__device__ __forceinline__ ULL ld_hint64(const void* p, ULL pol) {
    ULL v;
    asm("ld.global.nc.L2::cache_hint.b64 %0, [%1], %2;"
        : "=l"(v) : "l"(p), "l"(pol));
    return v;
}
__device__ __forceinline__ void st_hint32(void* p, unsigned v, ULL pol) {
    asm volatile("st.global.L2::cache_hint.b32 [%0], %1, %2;"
                 :: "l"(p), "r"(v), "l"(pol) : "memory");
}
__device__ __forceinline__ float4 ld_hint_f4(const void* p, ULL pol) {
    float4 v;
    asm("ld.global.nc.L2::cache_hint.v4.f32 {%0,%1,%2,%3}, [%4], %5;"
        : "=f"(v.x), "=f"(v.y), "=f"(v.z), "=f"(v.w) : "l"(p), "l"(pol));
    return v;
}
__device__ __forceinline__ void st_hint_f4(void* p, float4 v, ULL pol) {
    asm volatile("st.global.L2::cache_hint.v4.f32 [%0], {%1,%2,%3,%4}, %5;"
                 :: "l"(p), "f"(v.x), "f"(v.y), "f"(v.z), "f"(v.w), "l"(pol)
                 : "memory");
}
__device__ __forceinline__ void st_hint_f2(void* p, float2 v, ULL pol) {
    asm volatile("st.global.L2::cache_hint.v2.f32 [%0], {%1,%2}, %3;"
                 :: "l"(p), "f"(v.x), "f"(v.y), "l"(pol) : "memory");
}

// ---------------- CSR build (3 kernels) -------------------------------------
// count: histogram over dst; also re-zero lookback flags for this call
__global__ void k_count(const int* __restrict__ dst, int* cnt, int* bflag, int e) {
    int i = blockIdx.x * blockDim.x + threadIdx.x;
    if (i < NB) bflag[i] = 0;
    if (i < e) atomicAdd(&cnt[dst[i]], 1);
}

// single-pass scan with decoupled lookback; also dinv + cnt re-zero + cursor
__global__ void k_scanlb(int* cnt, int* rowstart, int* cursor, float* dinv,
                         int* bagg, int* bpre, int* bflag, int e, int n) {
    __shared__ int sh[SEG];
    __shared__ int s_run;
    const int b = blockIdx.x;
    const int tid = threadIdx.x;
    const int i = b * SEG + tid;

    int v = (i < n) ? cnt[i] : 0;
    sh[tid] = v;
    __syncthreads();
#pragma unroll
    for (int o = 1; o < SEG; o <<= 1) {
        int t = (tid >= o) ? sh[tid - o] : 0;
        __syncthreads();
        sh[tid] += t;
        __syncthreads();
    }
    int excl = sh[tid] - v;
    int total = sh[SEG - 1];

    if (tid == 0) {
        if (b == 0) {
            bpre[0] = 0;
            bagg[0] = total;
            __threadfence();
            atomicExch(&bflag[0], 2);
            s_run = 0;
        } else {
            bagg[b] = total;
            __threadfence();
            atomicExch(&bflag[b], 1);
            int running = 0;
            int j = b - 1;
            while (j >= 0) {
                int f;
                do { f = atomicAdd(&bflag[j], 0); } while (f == 0);
                if (f == 2) { running += bpre[j] + bagg[j]; break; }
                running += bagg[j];
                --j;
            }
            bpre[b] = running;
            __threadfence();
            atomicExch(&bflag[b], 2);
            s_run = running;
        }
    }
    __syncthreads();
    int run = s_run;

    if (i < n) {
        int r = excl + run;
        rowstart[i] = r;
        cursor[i]   = r;
        dinv[i]     = rsqrtf((float)(v + 1));
        cnt[i]      = 0;                    // restore for next call
    }
    if (b == 0 && tid == 0) rowstart[n] = e;
}

__global__ void k_scatter(const int* __restrict__ src, const int* __restrict__ dst,
                          const float* __restrict__ dinv, int* cursor,
                          int* csr_src, float* csr_w, int e) {
    int i = blockIdx.x * blockDim.x + threadIdx.x;
    if (i >= e) return;
    int s = src[i], d = dst[i];
    int p = atomicAdd(&cursor[d], 1);
    csr_src[p] = s;
    csr_w[p]   = dinv[s] * dinv[d];
}

// ---------------------------------------------------------------------------
// layer-0 gather on raw x (fp32): g[v] = dinv^2 x[v] + sum w x[src]
// (4th kernel launch -> ncu target)
// ---------------------------------------------------------------------------
__global__ void k_gather_x(const float* __restrict__ x,
                           const float* __restrict__ dinv,
                           const int* __restrict__ rowstart,
                           const int* __restrict__ csr_src,
                           const float* __restrict__ csr_w,
                           float* __restrict__ out, int n) {
    int v = (blockIdx.x * blockDim.x + threadIdx.x) >> 5;
    int lane = threadIdx.x & 31;
    if (v >= n) return;

    const ULL polLast  = policy_evict_last();
    const ULL polFirst = policy_evict_first();

    int beg = rowstart[v];
    int end = rowstart[v + 1];
    float dv = dinv[v];
    float sl = dv * dv;
    const size_t lo = (size_t)(lane << 2);

    float4 acc = ld_hint_f4(x + (size_t)v * 128 + lo, polLast);
    acc.x *= sl; acc.y *= sl; acc.z *= sl; acc.w *= sl;

    int i = beg;
    for (; i + 3 < end; i += 4) {
        int   s0 = csr_src[i],     s1 = csr_src[i + 1];
        int   s2 = csr_src[i + 2], s3 = csr_src[i + 3];
        float w0 = csr_w[i],       w1 = csr_w[i + 1];
        float w2 = csr_w[i + 2],   w3 = csr_w[i + 3];
        float4 x0 = ld_hint_f4(x + (size_t)s0 * 128 + lo, polLast);
        float4 x1 = ld_hint_f4(x + (size_t)s1 * 128 + lo, polLast);
        float4 x2 = ld_hint_f4(x + (size_t)s2 * 128 + lo, polLast);
        float4 x3 = ld_hint_f4(x + (size_t)s3 * 128 + lo, polLast);
        acc.x = fmaf(w0, x0.x, acc.x); acc.y = fmaf(w0, x0.y, acc.y);
        acc.z = fmaf(w0, x0.z, acc.z); acc.w = fmaf(w0, x0.w, acc.w);
        acc.x = fmaf(w1, x1.x, acc.x); acc.y = fmaf(w1, x1.y, acc.y);
        acc.z = fmaf(w1, x1.z, acc.z); acc.w = fmaf(w1, x1.w, acc.w);
        acc.x = fmaf(w2, x2.x, acc.x); acc.y = fmaf(w2, x2.y, acc.y);
        acc.z = fmaf(w2, x2.z, acc.z); acc.w = fmaf(w2, x2.w, acc.w);
        acc.x = fmaf(w3, x3.x, acc.x); acc.y = fmaf(w3, x3.y, acc.y);
        acc.z = fmaf(w3, x3.z, acc.z); acc.w = fmaf(w3, x3.w, acc.w);
    }
    for (; i < end; i++) {
        int   s0 = csr_src[i];
        float w0 = csr_w[i];
        float4 x0 = ld_hint_f4(x + (size_t)s0 * 128 + lo, polLast);
        acc.x = fmaf(w0, x0.x, acc.x); acc.y = fmaf(w0, x0.y, acc.y);
        acc.z = fmaf(w0, x0.z, acc.z); acc.w = fmaf(w0, x0.w, acc.w);
    }

    st_hint_f4(out + (size_t)v * 128 + lo, acc, polFirst);
}

// ---------------------------------------------------------------------------
// tf32 tensor-core GEMM: C[M,128] = A[M,128] @ B[128,128]
// optional bias+relu epilogue; optional bf16 shadow
// ---------------------------------------------------------------------------
__global__ void __launch_bounds__(256)
k_gemm_tf32(const float* __restrict__ A,
            const float* __restrict__ B,
            float* __restrict__ Cm,
            __nv_bfloat16* __restrict__ Cb,     // may be nullptr
            const float* __restrict__ bias,     // may be nullptr (implies no relu)
            int M) {
    __shared__ unsigned AsT[32][136];
    __shared__ unsigned Bs [32][136];

    const int tid  = threadIdx.x;
    const int lane = tid & 31;
    const int wid  = tid >> 5;
    const int warp_m = wid & 3;
    const int warp_n = wid >> 2;
    const int rowBase = blockIdx.x * 128;

    const int r = lane >> 2;
    const int t = lane & 3;

    float acc[2][8][4];
#pragma unroll
    for (int i = 0; i < 2; i++)
#pragma unroll
        for (int j = 0; j < 8; j++)
#pragma unroll
            for (int q = 0; q < 4; q++) acc[i][j][q] = 0.0f;

    for (int k0 = 0; k0 < 128; k0 += 32) {
#pragma unroll
        for (int it = 0; it < 4; it++) {
            int idx = tid + it * 256;
            int m   = idx & 127;
            int kq  = idx >> 7;
            int gr  = rowBase + m;
            float4 v = make_float4(0.f, 0.f, 0.f, 0.f);
            if (gr < M) v = *(const float4*)(A + (size_t)gr * 128 + k0 + kq * 4);
            AsT[kq * 4 + 0][m] = cvt_tf32(v.x);
            AsT[kq * 4 + 1][m] = cvt_tf32(v.y);
            AsT[kq * 4 + 2][m] = cvt_tf32(v.z);
            AsT[kq * 4 + 3][m] = cvt_tf32(v.w);
        }
#pragma unroll
        for (int it = 0; it < 4; it++) {
            int idx = tid + it * 256;
            int k   = idx >> 5;
            int n4  = (idx & 31) << 2;
            float4 v = *(const float4*)(B + (size_t)(k0 + k) * 128 + n4);
            uint4 u = make_uint4(cvt_tf32(v.x), cvt_tf32(v.y),
                                 cvt_tf32(v.z), cvt_tf32(v.w));
            *(uint4*)&Bs[k][n4] = u;
        }
        __syncthreads();

#pragma unroll
        for (int ks = 0; ks < 4; ks++) {
            const int kb = ks * 8;
            unsigned a[2][4];
#pragma unroll
            for (int fm = 0; fm < 2; fm++) {
                int mb = warp_m * 32 + fm * 16;
                a[fm][0] = AsT[kb + t    ][mb + r];
                a[fm][1] = AsT[kb + t    ][mb + r + 8];
                a[fm][2] = AsT[kb + t + 4][mb + r];
                a[fm][3] = AsT[kb + t + 4][mb + r + 8];
            }
#pragma unroll
            for (int fn = 0; fn < 8; fn++) {
                int nb = warp_n * 64 + fn * 8;
                unsigned b0 = Bs[kb + t    ][nb + r];
                unsigned b1 = Bs[kb + t + 4][nb + r];
#pragma unroll
                for (int fm = 0; fm < 2; fm++) {
                    asm("mma.sync.aligned.m16n8k8.row.col.f32.tf32.tf32.f32 "
                        "{%0,%1,%2,%3}, {%4,%5,%6,%7}, {%8,%9}, {%0,%1,%2,%3};"
                        : "+f"(acc[fm][fn][0]), "+f"(acc[fm][fn][1]),
                          "+f"(acc[fm][fn][2]), "+f"(acc[fm][fn][3])
                        : "r"(a[fm][0]), "r"(a[fm][1]), "r"(a[fm][2]), "r"(a[fm][3]),
                          "r"(b0), "r"(b1));
                }
            }
        }
        __syncthreads();
    }

    const ULL polLast  = policy_evict_last();
    const ULL polFirst = policy_evict_first();

#pragma unroll
    for (int fm = 0; fm < 2; fm++) {
        int r0 = rowBase + warp_m * 32 + fm * 16 + r;
        int r1 = r0 + 8;
#pragma unroll
        for (int fn = 0; fn < 8; fn++) {
            int col = warp_n * 64 + fn * 8 + 2 * t;
            float2 bb = make_float2(0.f, 0.f);
            if (bias) bb = *(const float2*)(bias + col);
#pragma unroll
            for (int half = 0; half < 2; half++) {
                int rr = half ? r1 : r0;
                if (rr >= M) continue;
                float2 v = half ? make_float2(acc[fm][fn][2], acc[fm][fn][3])
                                : make_float2(acc[fm][fn][0], acc[fm][fn][1]);
                if (bias) {
                    v.x = fmaxf(v.x + bb.x, 0.f);
                    v.y = fmaxf(v.y + bb.y, 0.f);
                }
                st_hint_f2(Cm + (size_t)rr * 128 + col, v, polFirst);
                if (Cb) {
                    __nv_bfloat162 h = __float22bfloat162_rn(v);
                    st_hint32(Cb + (size_t)rr * 128 + col, *(unsigned*)&h, polLast);
                }
            }
        }
    }
}

// ---------------------------------------------------------------------------
// layer-1 fused gather: agg = relu(Â t + b) + res   (neighbors from bf16 shadow)
// ---------------------------------------------------------------------------
__device__ __forceinline__ void acc_bf16(float4& acc, float w, ULL packed) {
    __nv_bfloat162 lo = *(__nv_bfloat162*)&packed;
    __nv_bfloat162 hi = *((__nv_bfloat162*)&packed + 1);
    float2 f0 = __bfloat1622float2(lo);
    float2 f1 = __bfloat1622float2(hi);
    acc.x = fmaf(w, f0.x, acc.x);
    acc.y = fmaf(w, f0.y, acc.y);
    acc.z = fmaf(w, f1.x, acc.z);
    acc.w = fmaf(w, f1.y, acc.w);
}

__global__ void k_gather(const float* __restrict__ lin,
                         const __nv_bfloat16* __restrict__ linb,
                         const float* __restrict__ dinv,
                         const int* __restrict__ rowstart,
                         const int* __restrict__ csr_src,
                         const float* __restrict__ csr_w,
                         const float* __restrict__ bias,
                         const float* __restrict__ res,
                         float* __restrict__ out, int n) {
    int v = (blockIdx.x * blockDim.x + threadIdx.x) >> 5;
    int lane = threadIdx.x & 31;
    if (v >= n) return;

    const ULL polLast  = policy_evict_last();
    const ULL polFirst = policy_evict_first();

    int beg = rowstart[v];
    int end = rowstart[v + 1];
    float dv = dinv[v];
    float sl = dv * dv;
    const size_t lo = (size_t)(lane << 2);

    float4 acc = ld_hint_f4(lin + (size_t)v * 128 + lo, polFirst);
    acc.x *= sl; acc.y *= sl; acc.z *= sl; acc.w *= sl;

    int i = beg;
    for (; i + 3 < end; i += 4) {
        int   s0 = csr_src[i],     s1 = csr_src[i + 1];
        int   s2 = csr_src[i + 2], s3 = csr_src[i + 3];
        float w0 = csr_w[i],       w1 = csr_w[i + 1];
        float w2 = csr_w[i + 2],   w3 = csr_w[i + 3];
        ULL x0 = ld_hint64(linb + (size_t)s0 * 128 + lo, polLast);
        ULL x1 = ld_hint64(linb + (size_t)s1 * 128 + lo, polLast);
        ULL x2 = ld_hint64(linb + (size_t)s2 * 128 + lo, polLast);
        ULL x3 = ld_hint64(linb + (size_t)s3 * 128 + lo, polLast);
        acc_bf16(acc, w0, x0);
        acc_bf16(acc, w1, x1);
        acc_bf16(acc, w2, x2);
        acc_bf16(acc, w3, x3);
    }
    for (; i < end; i++) {
        int   s0 = csr_src[i];
        float w0 = csr_w[i];
        ULL x0 = ld_hint64(linb + (size_t)s0 * 128 + lo, polLast);
        acc_bf16(acc, w0, x0);
    }

    float4 bb = ((const float4*)bias)[lane];
    acc.x = fmaxf(acc.x + bb.x, 0.f);
    acc.y = fmaxf(acc.y + bb.y, 0.f);
    acc.z = fmaxf(acc.z + bb.z, 0.f);
    acc.w = fmaxf(acc.w + bb.w, 0.f);
    float4 rr = ld_hint_f4(res + (size_t)v * 128 + lo, polFirst);
    acc.x += rr.x; acc.y += rr.y; acc.z += rr.z; acc.w += rr.w;
    st_hint_f4(out + (size_t)v * 128 + lo, acc, polFirst);
}

// ---------------------------------------------------------------------------
// classifier GEMM + fused log_softmax (packed f32x2)
// ---------------------------------------------------------------------------
__global__ void k_cls_gemm(const float* __restrict__ h,
                           const float* __restrict__ wl,
                           const float* __restrict__ bl,
                           float* __restrict__ out, int n) {
    __shared__ float AsT[16][258];
    __shared__ float Bsf[16 * C];
    __shared__ float sbl[C];

    const int tx = threadIdx.x & 7;
    const int ty = threadIdx.x >> 3;
    const int rowBase = blockIdx.x * 256;

    if (threadIdx.x < C) sbl[threadIdx.x] = bl[threadIdx.x];

    ULL acc[4][5];
#pragma unroll
    for (int i = 0; i < 4; i++)
#pragma unroll
        for (int j = 0; j < 5; j++) acc[i][j] = 0ull;

    const int gr = rowBase + threadIdx.x;

    for (int k0 = 0; k0 < 128; k0 += 16) {
#pragma unroll
        for (int i = 0; i < 4; i++) {
            float4 v = make_float4(0.f, 0.f, 0.f, 0.f);
            if (gr < n) v = *(const float4*)(h + (size_t)gr * 128 + k0 + i * 4);
            AsT[i * 4 + 0][threadIdx.x] = v.x;
            AsT[i * 4 + 1][threadIdx.x] = v.y;
            AsT[i * 4 + 2][threadIdx.x] = v.z;
            AsT[i * 4 + 3][threadIdx.x] = v.w;
        }
        for (int i = threadIdx.x; i < 16 * C; i += 256)
            Bsf[i] = wl[k0 * C + i];
        __syncthreads();

#pragma unroll 4
        for (int kk = 0; kk < 16; kk++) {
            ULL a0 = *(const ULL*)&AsT[kk][ty * 8 + 0];
            ULL a1 = *(const ULL*)&AsT[kk][ty * 8 + 2];
            ULL a2 = *(const ULL*)&AsT[kk][ty * 8 + 4];
            ULL a3 = *(const ULL*)&AsT[kk][ty * 8 + 6];
            const float* bp = &Bsf[kk * C + tx * 5];
            ULL b0 = fdup(bp[0]), b1 = fdup(bp[1]), b2 = fdup(bp[2]);
            ULL b3 = fdup(bp[3]), b4 = fdup(bp[4]);
#define CLS_ROW(i, ai) \
            acc[i][0] = ffma2(ai, b0, acc[i][0]); \
            acc[i][1] = ffma2(ai, b1, acc[i][1]); \
            acc[i][2] = ffma2(ai, b2, acc[i][2]); \
            acc[i][3] = ffma2(ai, b3, acc[i][3]); \
            acc[i][4] = ffma2(ai, b4, acc[i][4]);
            CLS_ROW(0, a0) CLS_ROW(1, a1) CLS_ROW(2, a2) CLS_ROW(3, a3)
#undef CLS_ROW
        }
        __syncthreads();
    }

    const float bb0 = sbl[tx * 5 + 0], bb1 = sbl[tx * 5 + 1], bb2 = sbl[tx * 5 + 2];
    const float bb3 = sbl[tx * 5 + 3], bb4 = sbl[tx * 5 + 4];

#pragma unroll
    for (int i = 0; i < 4; i++) {
#pragma unroll
        for (int half = 0; half < 2; half++) {
            int r0 = rowBase + ty * 8 + 2 * i + half;
            float2 q0 = *(float2*)&acc[i][0];
            float2 q1 = *(float2*)&acc[i][1];
            float2 q2 = *(float2*)&acc[i][2];
            float2 q3 = *(float2*)&acc[i][3];
            float2 q4 = *(float2*)&acc[i][4];
            float l0 = (half ? q0.y : q0.x) + bb0;
            float l1 = (half ? q1.y : q1.x) + bb1;
            float l2 = (half ? q2.y : q2.x) + bb2;
            float l3 = (half ? q3.y : q3.x) + bb3;
            float l4 = (half ? q4.y : q4.x) + bb4;

            float m = fmaxf(fmaxf(fmaxf(l0, l1), fmaxf(l2, l3)), l4);
            m = fmaxf(m, __shfl_xor_sync(0xffffffffu, m, 1));
            m = fmaxf(m, __shfl_xor_sync(0xffffffffu, m, 2));
            m = fmaxf(m, __shfl_xor_sync(0xffffffffu, m, 4));
            float se = __expf(l0 - m) + __expf(l1 - m) + __expf(l2 - m)
                     + __expf(l3 - m) + __expf(l4 - m);
            se += __shfl_xor_sync(0xffffffffu, se, 1);
            se += __shfl_xor_sync(0xffffffffu, se, 2);
            se += __shfl_xor_sync(0xffffffffu, se, 4);
            float lse = __logf(se) + m;

            if (r0 < n) {
                float* op = out + (size_t)r0 * C + tx * 5;
                op[0] = l0 - lse; op[1] = l1 - lse; op[2] = l2 - lse;
                op[3] = l3 - lse; op[4] = l4 - lse;
            }
        }
    }
}

// ---------------------------------------------------------------------------
// launch — single stream; gather_x is the 4th kernel (ncu target)
// ---------------------------------------------------------------------------
extern "C" void kernel_launch(void* const* d_in, const int* in_sizes, int n_in,
                              void* d_out, int out_size) {
    const float* x   = (const float*)d_in[0];
    const int*   ei  = (const int*)d_in[1];
    const float* w0  = (const float*)d_in[2];
    const float* b0  = (const float*)d_in[3];
    const float* w1  = (const float*)d_in[4];
    const float* b1  = (const float*)d_in[5];
    const float* wl  = (const float*)d_in[6];
    const float* bl  = (const float*)d_in[7];
    float* out = (float*)d_out;

    const int n = in_sizes[0] / H;
    const int e = in_sizes[1] / 2;
    const int* src = ei;
    const int* dst = ei + e;

    float *dinv, *lin, *agg, *h0, *csr_w;
    __nv_bfloat16* linb;
    int *cnt, *rowstart, *cursor, *csr_src, *bagg, *bpre, *bflag;
    cudaGetSymbolAddress((void**)&dinv,     g_dinv);
    cudaGetSymbolAddress((void**)&cnt,      g_cnt);
    cudaGetSymbolAddress((void**)&rowstart, g_rowstart);
    cudaGetSymbolAddress((void**)&cursor,   g_cursor);
    cudaGetSymbolAddress((void**)&bagg,     g_bagg);
    cudaGetSymbolAddress((void**)&bpre,     g_bpre);
    cudaGetSymbolAddress((void**)&bflag,    g_bflag);
    cudaGetSymbolAddress((void**)&csr_src,  g_csr_src);
    cudaGetSymbolAddress((void**)&csr_w,    g_csr_w);
    cudaGetSymbolAddress((void**)&lin,      g_lin);
    cudaGetSymbolAddress((void**)&linb,     g_linb);
    cudaGetSymbolAddress((void**)&agg,      g_agg);
    cudaGetSymbolAddress((void**)&h0,       g_h0);

    const int TB = 256;
    const int nb = (n + SEG - 1) / SEG;
    const int gemmBlocks   = (n + 127) / 128;
    const int gatherBlocks = (n * 32 + TB - 1) / TB;

    // CSR build: 3 kernels
    k_count  <<<(e + TB - 1) / TB, TB>>>(dst, cnt, bflag, e);
    k_scanlb <<<nb, SEG>>>(cnt, rowstart, cursor, dinv, bagg, bpre, bflag, e, n);
    k_scatter<<<(e + TB - 1) / TB, TB>>>(src, dst, dinv, cursor, csr_src, csr_w, e);

    // layer 0: gather first (linearity: Â(xW) == (Âx)W), then GEMM w/ bias+relu
    k_gather_x <<<gatherBlocks, TB>>>(x, dinv, rowstart, csr_src, csr_w, agg, n);
    k_gemm_tf32<<<gemmBlocks, TB>>>(agg, w0, h0, nullptr, b0, n);

    // layer 1: GEMM (emit bf16 shadow), gather w/ bias+relu+residual
    k_gemm_tf32<<<gemmBlocks, TB>>>(h0, w1, lin, linb, nullptr, n);
    k_gather   <<<gatherBlocks, TB>>>(lin, linb, dinv, rowstart, csr_src, csr_w,
                                      b1, h0, agg, n);

    // classifier + fused log_softmax
    k_cls_gemm<<<(n + 255) / 256, TB>>>(agg, wl, bl, out, n);
}

// round 12
// speedup vs baseline: 1.0583x; 1.0583x over previous
#include <cuda_runtime.h>
#include <math.h>

#define NMAX 100000
#define EMAX 1600000
#define H 128
#define C 40
#define SEG 512
#define NB ((NMAX + SEG - 1) / SEG)

typedef unsigned long long ULL;

// ---------------- scratch -------------------------------------------------
__device__ float g_dinv[NMAX];
__device__ int   g_cnt[NMAX];
__device__ int   g_rowstart[NMAX + 1];
__device__ int   g_cursor[NMAX];
__device__ int   g_bagg[NB];
__device__ int   g_bpre[NB];
__device__ int   g_bflag[NB];
__device__ int   g_csr_src[EMAX];
__device__ float g_csr_w[EMAX];
__device__ float g_lin[(size_t)NMAX * H];
__device__ float g_agg[(size_t)NMAX * H];
__device__ float g_h0 [(size_t)NMAX * H];

// ---------------- helpers ---------------------------------------------------
__device__ __forceinline__ ULL ffma2(ULL a, ULL b, ULL c) {
    ULL d;
    asm("fma.rn.f32x2 %0, %1, %2, %3;" : "=l"(d) : "l"(a), "l"(b), "l"(c));
    return d;
}
__device__ __forceinline__ ULL fdup(float x) {
    ULL r;
    asm("mov.b64 %0, {%1, %1};" : "=l"(r) : "f"(x));
    return r;
}
__device__ __forceinline__ unsigned cvt_tf32(float f) {
    unsigned u;
    asm("cvt.rna.tf32.f32 %0, %1;" : "=r"(u) : "f"(f));
    return u;
}
__device__ __forceinline__ ULL policy_evict_last() {
    ULL pol;
    asm("createpolicy.fractional.L2::evict_last.b64 %0, 1.0;" : "=l"(pol));
    return pol;
}
__device__ __forceinline__ ULL policy_evict_first() {
    ULL pol;
    asm("createpolicy.fractional.L2::evict_first.b64 %0, 1.0;" : "=l"(pol));
    return pol;
}
__device__ __forceinline__ float4 ld_hint_f4(const void* p, ULL pol) {
    float4 v;
    asm("ld.global.nc.L2::cache_hint.v4.f32 {%0,%1,%2,%3}, [%4], %5;"
        : "=f"(v.x), "=f"(v.y), "=f"(v.z), "=f"(v.w) : "l"(p), "l"(pol));
    return v;
}
__device__ __forceinline__ void st_hint_f4(void* p, float4 v, ULL pol) {
    asm volatile("st.global.L2::cache_hint.v4.f32 [%0], {%1,%2,%3,%4}, %5;"
                 :: "l"(p), "f"(v.x), "f"(v.y), "f"(v.z), "f"(v.w), "l"(pol)
                 : "memory");
}
__device__ __forceinline__ void st_hint_f2(void* p, float2 v, ULL pol) {
    asm volatile("st.global.L2::cache_hint.v2.f32 [%0], {%1,%2}, %3;"
                 :: "l"(p), "f"(v.x), "f"(v.y), "l"(pol) : "memory");
}

// ---------------- CSR build (3 kernels) -------------------------------------
__global__ void k_count(const int* __restrict__ dst, int* cnt, int* bflag, int e) {
    int i = blockIdx.x * blockDim.x + threadIdx.x;
    if (i < NB) bflag[i] = 0;
    if (i < e) atomicAdd(&cnt[dst[i]], 1);
}

__global__ void k_scanlb(int* cnt, int* rowstart, int* cursor, float* dinv,
                         int* bagg, int* bpre, int* bflag, int e, int n) {
    __shared__ int sh[SEG];
    __shared__ int s_run;
    const int b = blockIdx.x;
    const int tid = threadIdx.x;
    const int i = b * SEG + tid;

    int v = (i < n) ? cnt[i] : 0;
    sh[tid] = v;
    __syncthreads();
#pragma unroll
    for (int o = 1; o < SEG; o <<= 1) {
        int t = (tid >= o) ? sh[tid - o] : 0;
        __syncthreads();
        sh[tid] += t;
        __syncthreads();
    }
    int excl = sh[tid] - v;
    int total = sh[SEG - 1];

    if (tid == 0) {
        if (b == 0) {
            bpre[0] = 0;
            bagg[0] = total;
            __threadfence();
            atomicExch(&bflag[0], 2);
            s_run = 0;
        } else {
            bagg[b] = total;
            __threadfence();
            atomicExch(&bflag[b], 1);
            int running = 0;
            int j = b - 1;
            while (j >= 0) {
                int f;
                do { f = atomicAdd(&bflag[j], 0); } while (f == 0);
                if (f == 2) { running += bpre[j] + bagg[j]; break; }
                running += bagg[j];
                --j;
            }
            bpre[b] = running;
            __threadfence();
            atomicExch(&bflag[b], 2);
            s_run = running;
        }
    }
    __syncthreads();
    int run = s_run;

    if (i < n) {
        int r = excl + run;
        rowstart[i] = r;
        cursor[i]   = r;
        dinv[i]     = rsqrtf((float)(v + 1));
        cnt[i]      = 0;
    }
    if (b == 0 && tid == 0) rowstart[n] = e;
}

__global__ void k_scatter(const int* __restrict__ src, const int* __restrict__ dst,
                          const float* __restrict__ dinv, int* cursor,
                          int* csr_src, float* csr_w, int e) {
    int i = blockIdx.x * blockDim.x + threadIdx.x;
    if (i >= e) return;
    int s = src[i], d = dst[i];
    int p = atomicAdd(&cursor[d], 1);
    csr_src[p] = s;
    csr_w[p]   = dinv[s] * dinv[d];
}

// ---------------------------------------------------------------------------
// fp32 fused gather (warp per dst node, unroll 4):
//   out = relu(dinv^2*feat[v] + sum w*feat[src] + bias) [+ res]
// ---------------------------------------------------------------------------
__global__ void k_gather(const float* __restrict__ feat,
                         const float* __restrict__ dinv,
                         const int* __restrict__ rowstart,
                         const int* __restrict__ csr_src,
                         const float* __restrict__ csr_w,
                         const float* __restrict__ bias,
                         const float* __restrict__ res,     // may be nullptr
                         float* __restrict__ out, int n) {
    int v = (blockIdx.x * blockDim.x + threadIdx.x) >> 5;
    int lane = threadIdx.x & 31;
    if (v >= n) return;

    const ULL polLast  = policy_evict_last();
    const ULL polFirst = policy_evict_first();

    int beg = rowstart[v];
    int end = rowstart[v + 1];
    float dv = dinv[v];
    float sl = dv * dv;
    const size_t lo = (size_t)(lane << 2);

    float4 acc = ld_hint_f4(feat + (size_t)v * 128 + lo, polLast);
    acc.x *= sl; acc.y *= sl; acc.z *= sl; acc.w *= sl;

    int i = beg;
    for (; i + 3 < end; i += 4) {
        int   s0 = csr_src[i],     s1 = csr_src[i + 1];
        int   s2 = csr_src[i + 2], s3 = csr_src[i + 3];
        float w0 = csr_w[i],       w1 = csr_w[i + 1];
        float w2 = csr_w[i + 2],   w3 = csr_w[i + 3];
        float4 x0 = ld_hint_f4(feat + (size_t)s0 * 128 + lo, polLast);
        float4 x1 = ld_hint_f4(feat + (size_t)s1 * 128 + lo, polLast);
        float4 x2 = ld_hint_f4(feat + (size_t)s2 * 128 + lo, polLast);
        float4 x3 = ld_hint_f4(feat + (size_t)s3 * 128 + lo, polLast);
        acc.x = fmaf(w0, x0.x, acc.x); acc.y = fmaf(w0, x0.y, acc.y);
        acc.z = fmaf(w0, x0.z, acc.z); acc.w = fmaf(w0, x0.w, acc.w);
        acc.x = fmaf(w1, x1.x, acc.x); acc.y = fmaf(w1, x1.y, acc.y);
        acc.z = fmaf(w1, x1.z, acc.z); acc.w = fmaf(w1, x1.w, acc.w);
        acc.x = fmaf(w2, x2.x, acc.x); acc.y = fmaf(w2, x2.y, acc.y);
        acc.z = fmaf(w2, x2.z, acc.z); acc.w = fmaf(w2, x2.w, acc.w);
        acc.x = fmaf(w3, x3.x, acc.x); acc.y = fmaf(w3, x3.y, acc.y);
        acc.z = fmaf(w3, x3.z, acc.z); acc.w = fmaf(w3, x3.w, acc.w);
    }
    for (; i < end; i++) {
        int   s0 = csr_src[i];
        float w0 = csr_w[i];
        float4 x0 = ld_hint_f4(feat + (size_t)s0 * 128 + lo, polLast);
        acc.x = fmaf(w0, x0.x, acc.x); acc.y = fmaf(w0, x0.y, acc.y);
        acc.z = fmaf(w0, x0.z, acc.z); acc.w = fmaf(w0, x0.w, acc.w);
    }

    float4 bb = ((const float4*)bias)[lane];
    acc.x = fmaxf(acc.x + bb.x, 0.f);
    acc.y = fmaxf(acc.y + bb.y, 0.f);
    acc.z = fmaxf(acc.z + bb.z, 0.f);
    acc.w = fmaxf(acc.w + bb.w, 0.f);
    if (res) {
        float4 rr = ld_hint_f4(res + (size_t)v * 128 + lo, polFirst);
        acc.x += rr.x; acc.y += rr.y; acc.z += rr.z; acc.w += rr.w;
    }
    st_hint_f4(out + (size_t)v * 128 + lo, acc, polFirst);
}

// ---------------------------------------------------------------------------
// tf32 tensor-core GEMM: C[M,128] = A[M,128] @ B[128,128]  (no shadow)
// ---------------------------------------------------------------------------
__global__ void __launch_bounds__(256)
k_gemm_tf32(const float* __restrict__ A,
            const float* __restrict__ B,
            float* __restrict__ Cm, int M) {
    __shared__ unsigned AsT[32][136];
    __shared__ unsigned Bs [32][136];

    const int tid  = threadIdx.x;
    const int lane = tid & 31;
    const int wid  = tid >> 5;
    const int warp_m = wid & 3;
    const int warp_n = wid >> 2;
    const int rowBase = blockIdx.x * 128;

    const int r = lane >> 2;
    const int t = lane & 3;

    float acc[2][8][4];
#pragma unroll
    for (int i = 0; i < 2; i++)
#pragma unroll
        for (int j = 0; j < 8; j++)
#pragma unroll
            for (int q = 0; q < 4; q++) acc[i][j][q] = 0.0f;

    for (int k0 = 0; k0 < 128; k0 += 32) {
#pragma unroll
        for (int it = 0; it < 4; it++) {
            int idx = tid + it * 256;
            int m   = idx & 127;
            int kq  = idx >> 7;
            int gr  = rowBase + m;
            float4 v = make_float4(0.f, 0.f, 0.f, 0.f);
            if (gr < M) v = *(const float4*)(A + (size_t)gr * 128 + k0 + kq * 4);
            AsT[kq * 4 + 0][m] = cvt_tf32(v.x);
            AsT[kq * 4 + 1][m] = cvt_tf32(v.y);
            AsT[kq * 4 + 2][m] = cvt_tf32(v.z);
            AsT[kq * 4 + 3][m] = cvt_tf32(v.w);
        }
#pragma unroll
        for (int it = 0; it < 4; it++) {
            int idx = tid + it * 256;
            int k   = idx >> 5;
            int n4  = (idx & 31) << 2;
            float4 v = *(const float4*)(B + (size_t)(k0 + k) * 128 + n4);
            uint4 u = make_uint4(cvt_tf32(v.x), cvt_tf32(v.y),
                                 cvt_tf32(v.z), cvt_tf32(v.w));
            *(uint4*)&Bs[k][n4] = u;
        }
        __syncthreads();

#pragma unroll
        for (int ks = 0; ks < 4; ks++) {
            const int kb = ks * 8;
            unsigned a[2][4];
#pragma unroll
            for (int fm = 0; fm < 2; fm++) {
                int mb = warp_m * 32 + fm * 16;
                a[fm][0] = AsT[kb + t    ][mb + r];
                a[fm][1] = AsT[kb + t    ][mb + r + 8];
                a[fm][2] = AsT[kb + t + 4][mb + r];
                a[fm][3] = AsT[kb + t + 4][mb + r + 8];
            }
#pragma unroll
            for (int fn = 0; fn < 8; fn++) {
                int nb = warp_n * 64 + fn * 8;
                unsigned b0 = Bs[kb + t    ][nb + r];
                unsigned b1 = Bs[kb + t + 4][nb + r];
#pragma unroll
                for (int fm = 0; fm < 2; fm++) {
                    asm("mma.sync.aligned.m16n8k8.row.col.f32.tf32.tf32.f32 "
                        "{%0,%1,%2,%3}, {%4,%5,%6,%7}, {%8,%9}, {%0,%1,%2,%3};"
                        : "+f"(acc[fm][fn][0]), "+f"(acc[fm][fn][1]),
                          "+f"(acc[fm][fn][2]), "+f"(acc[fm][fn][3])
                        : "r"(a[fm][0]), "r"(a[fm][1]), "r"(a[fm][2]), "r"(a[fm][3]),
                          "r"(b0), "r"(b1));
                }
            }
        }
        __syncthreads();
    }

    const ULL polLast = policy_evict_last();

#pragma unroll
    for (int fm = 0; fm < 2; fm++) {
        int r0 = rowBase + warp_m * 32 + fm * 16 + r;
        int r1 = r0 + 8;
#pragma unroll
        for (int fn = 0; fn < 8; fn++) {
            int col = warp_n * 64 + fn * 8 + 2 * t;
            if (r0 < M)
                st_hint_f2(Cm + (size_t)r0 * 128 + col,
                           make_float2(acc[fm][fn][0], acc[fm][fn][1]), polLast);
            if (r1 < M)
                st_hint_f2(Cm + (size_t)r1 * 128 + col,
                           make_float2(acc[fm][fn][2], acc[fm][fn][3]), polLast);
        }
    }
}

// ---------------------------------------------------------------------------
// classifier GEMM + fused log_softmax (packed f32x2)
// ---------------------------------------------------------------------------
__global__ void k_cls_gemm(const float* __restrict__ h,
                           const float* __restrict__ wl,
                           const float* __restrict__ bl,
                           float* __restrict__ out, int n) {
    __shared__ float AsT[16][258];
    __shared__ float Bsf[16 * C];
    __shared__ float sbl[C];

    const int tx = threadIdx.x & 7;
    const int ty = threadIdx.x >> 3;
    const int rowBase = blockIdx.x * 256;

    if (threadIdx.x < C) sbl[threadIdx.x] = bl[threadIdx.x];

    ULL acc[4][5];
#pragma unroll
    for (int i = 0; i < 4; i++)
#pragma unroll
        for (int j = 0; j < 5; j++) acc[i][j] = 0ull;

    const int gr = rowBase + threadIdx.x;

    for (int k0 = 0; k0 < 128; k0 += 16) {
#pragma unroll
        for (int i = 0; i < 4; i++) {
            float4 v = make_float4(0.f, 0.f, 0.f, 0.f);
            if (gr < n) v = *(const float4*)(h + (size_t)gr * 128 + k0 + i * 4);
            AsT[i * 4 + 0][threadIdx.x] = v.x;
            AsT[i * 4 + 1][threadIdx.x] = v.y;
            AsT[i * 4 + 2][threadIdx.x] = v.z;
            AsT[i * 4 + 3][threadIdx.x] = v.w;
        }
        for (int i = threadIdx.x; i < 16 * C; i += 256)
            Bsf[i] = wl[k0 * C + i];
        __syncthreads();

#pragma unroll 4
        for (int kk = 0; kk < 16; kk++) {
            ULL a0 = *(const ULL*)&AsT[kk][ty * 8 + 0];
            ULL a1 = *(const ULL*)&AsT[kk][ty * 8 + 2];
            ULL a2 = *(const ULL*)&AsT[kk][ty * 8 + 4];
            ULL a3 = *(const ULL*)&AsT[kk][ty * 8 + 6];
            const float* bp = &Bsf[kk * C + tx * 5];
            ULL b0 = fdup(bp[0]), b1 = fdup(bp[1]), b2 = fdup(bp[2]);
            ULL b3 = fdup(bp[3]), b4 = fdup(bp[4]);
#define CLS_ROW(i, ai) \
            acc[i][0] = ffma2(ai, b0, acc[i][0]); \
            acc[i][1] = ffma2(ai, b1, acc[i][1]); \
            acc[i][2] = ffma2(ai, b2, acc[i][2]); \
            acc[i][3] = ffma2(ai, b3, acc[i][3]); \
            acc[i][4] = ffma2(ai, b4, acc[i][4]);
            CLS_ROW(0, a0) CLS_ROW(1, a1) CLS_ROW(2, a2) CLS_ROW(3, a3)
#undef CLS_ROW
        }
        __syncthreads();
    }

    const float bb0 = sbl[tx * 5 + 0], bb1 = sbl[tx * 5 + 1], bb2 = sbl[tx * 5 + 2];
    const float bb3 = sbl[tx * 5 + 3], bb4 = sbl[tx * 5 + 4];

#pragma unroll
    for (int i = 0; i < 4; i++) {
#pragma unroll
        for (int half = 0; half < 2; half++) {
            int r0 = rowBase + ty * 8 + 2 * i + half;
            float2 q0 = *(float2*)&acc[i][0];
            float2 q1 = *(float2*)&acc[i][1];
            float2 q2 = *(float2*)&acc[i][2];
            float2 q3 = *(float2*)&acc[i][3];
            float2 q4 = *(float2*)&acc[i][4];
            float l0 = (half ? q0.y : q0.x) + bb0;
            float l1 = (half ? q1.y : q1.x) + bb1;
            float l2 = (half ? q2.y : q2.x) + bb2;
            float l3 = (half ? q3.y : q3.x) + bb3;
            float l4 = (half ? q4.y : q4.x) + bb4;

            float m = fmaxf(fmaxf(fmaxf(l0, l1), fmaxf(l2, l3)), l4);
            m = fmaxf(m, __shfl_xor_sync(0xffffffffu, m, 1));
            m = fmaxf(m, __shfl_xor_sync(0xffffffffu, m, 2));
            m = fmaxf(m, __shfl_xor_sync(0xffffffffu, m, 4));
            float se = __expf(l0 - m) + __expf(l1 - m) + __expf(l2 - m)
                     + __expf(l3 - m) + __expf(l4 - m);
            se += __shfl_xor_sync(0xffffffffu, se, 1);
            se += __shfl_xor_sync(0xffffffffu, se, 2);
            se += __shfl_xor_sync(0xffffffffu, se, 4);
            float lse = __logf(se) + m;

            if (r0 < n) {
                float* op = out + (size_t)r0 * C + tx * 5;
                op[0] = l0 - lse; op[1] = l1 - lse; op[2] = l2 - lse;
                op[3] = l3 - lse; op[4] = l4 - lse;
            }
        }
    }
}

// ---------------------------------------------------------------------------
// launch — CSR build forked onto stream 2, overlapping GEMM0
// ---------------------------------------------------------------------------
extern "C" void kernel_launch(void* const* d_in, const int* in_sizes, int n_in,
                              void* d_out, int out_size) {
    const float* x   = (const float*)d_in[0];
    const int*   ei  = (const int*)d_in[1];
    const float* w0  = (const float*)d_in[2];
    const float* b0  = (const float*)d_in[3];
    const float* w1  = (const float*)d_in[4];
    const float* b1  = (const float*)d_in[5];
    const float* wl  = (const float*)d_in[6];
    const float* bl  = (const float*)d_in[7];
    float* out = (float*)d_out;

    const int n = in_sizes[0] / H;
    const int e = in_sizes[1] / 2;
    const int* src = ei;
    const int* dst = ei + e;

    float *dinv, *lin, *agg, *h0, *csr_w;
    int *cnt, *rowstart, *cursor, *csr_src, *bagg, *bpre, *bflag;
    cudaGetSymbolAddress((void**)&dinv,     g_dinv);
    cudaGetSymbolAddress((void**)&cnt,      g_cnt);
    cudaGetSymbolAddress((void**)&rowstart, g_rowstart);
    cudaGetSymbolAddress((void**)&cursor,   g_cursor);
    cudaGetSymbolAddress((void**)&bagg,     g_bagg);
    cudaGetSymbolAddress((void**)&bpre,     g_bpre);
    cudaGetSymbolAddress((void**)&bflag,    g_bflag);
    cudaGetSymbolAddress((void**)&csr_src,  g_csr_src);
    cudaGetSymbolAddress((void**)&csr_w,    g_csr_w);
    cudaGetSymbolAddress((void**)&lin,      g_lin);
    cudaGetSymbolAddress((void**)&agg,      g_agg);
    cudaGetSymbolAddress((void**)&h0,       g_h0);

    static cudaStream_t s2 = nullptr;
    static cudaEvent_t evFork = nullptr, evJoin = nullptr;
    if (!s2) {
        cudaStreamCreateWithFlags(&s2, cudaStreamNonBlocking);
        cudaEventCreateWithFlags(&evFork, cudaEventDisableTiming);
        cudaEventCreateWithFlags(&evJoin, cudaEventDisableTiming);
    }

    const int TB = 256;
    const int nb = (n + SEG - 1) / SEG;
    const int gemmBlocks   = (n + 127) / 128;
    const int gatherBlocks = (n * 32 + TB - 1) / TB;

    // fork: CSR build on s2, GEMM0 on main
    cudaEventRecord(evFork, 0);
    cudaStreamWaitEvent(s2, evFork, 0);

    k_count  <<<(e + TB - 1) / TB, TB, 0, s2>>>(dst, cnt, bflag, e);
    k_scanlb <<<nb, SEG, 0, s2>>>(cnt, rowstart, cursor, dinv, bagg, bpre, bflag, e, n);
    k_scatter<<<(e + TB - 1) / TB, TB, 0, s2>>>(src, dst, dinv, cursor, csr_src, csr_w, e);
    cudaEventRecord(evJoin, s2);

    k_gemm_tf32<<<gemmBlocks, TB>>>(x, w0, lin, n);

    cudaStreamWaitEvent(0, evJoin, 0);

    // layer 0: gather w/ bias+relu (fp32 neighbors)
    k_gather<<<gatherBlocks, TB>>>(lin, dinv, rowstart, csr_src, csr_w,
                                   b0, nullptr, h0, n);
    // layer 1
    k_gemm_tf32<<<gemmBlocks, TB>>>(h0, w1, lin, n);
    k_gather<<<gatherBlocks, TB>>>(lin, dinv, rowstart, csr_src, csr_w,
                                   b1, h0, agg, n);
    // classifier + fused log_softmax
    k_cls_gemm<<<(n + 255) / 256, TB>>>(agg, wl, bl, out, n);
}

// round 16
// speedup vs baseline: 1.0587x; 1.0003x over previous
#include <cuda_runtime.h>
#include <math.h>

#define NMAX 100000
#define EMAX 1600000
#define H 128
#define C 40
#define SEG 512
#define NB ((NMAX + SEG - 1) / SEG)

typedef unsigned long long ULL;

// ---------------- scratch -------------------------------------------------
__device__ float g_dinv[NMAX];
__device__ int   g_cnt[NMAX];
__device__ int   g_rowstart[NMAX + 1];
__device__ int   g_cursor[NMAX];
__device__ int   g_bagg[NB];
__device__ int   g_bpre[NB];
__device__ int   g_bflag[NB];
__device__ int   g_csr_src[EMAX];
__device__ float g_csr_w[EMAX];
__device__ float g_lin[(size_t)NMAX * H];
__device__ float g_agg[(size_t)NMAX * H];
__device__ float g_h0 [(size_t)NMAX * H];

// ---------------- helpers ---------------------------------------------------
__device__ __forceinline__ ULL ffma2(ULL a, ULL b, ULL c) {
    ULL d;
    asm("fma.rn.f32x2 %0, %1, %2, %3;" : "=l"(d) : "l"(a), "l"(b), "l"(c));
    return d;
}
__device__ __forceinline__ ULL fdup(float x) {
    ULL r;
    asm("mov.b64 %0, {%1, %1};" : "=l"(r) : "f"(x));
    return r;
}
// round fp32 bits to nearest tf32 (ties up): add half-ULP of 10-bit mantissa
__device__ __forceinline__ unsigned rn_tf32(float f) {
    return __float_as_uint(f) + 0x1000u;
}
__device__ __forceinline__ ULL policy_evict_last() {
    ULL pol;
    asm("createpolicy.fractional.L2::evict_last.b64 %0, 1.0;" : "=l"(pol));
    return pol;
}
__device__ __forceinline__ ULL policy_evict_first() {
    ULL pol;
    asm("createpolicy.fractional.L2::evict_first.b64 %0, 1.0;" : "=l"(pol));
    return pol;
}
__device__ __forceinline__ float4 ld_hint_f4(const void* p, ULL pol) {
    float4 v;
    asm("ld.global.nc.L2::cache_hint.v4.f32 {%0,%1,%2,%3}, [%4], %5;"
        : "=f"(v.x), "=f"(v.y), "=f"(v.z), "=f"(v.w) : "l"(p), "l"(pol));
    return v;
}
__device__ __forceinline__ void st_hint_f4(void* p, float4 v, ULL pol) {
    asm volatile("st.global.L2::cache_hint.v4.f32 [%0], {%1,%2,%3,%4}, %5;"
                 :: "l"(p), "f"(v.x), "f"(v.y), "f"(v.z), "f"(v.w), "l"(pol)
                 : "memory");
}
__device__ __forceinline__ void st_hint_f2(void* p, float2 v, ULL pol) {
    asm volatile("st.global.L2::cache_hint.v2.f32 [%0], {%1,%2}, %3;"
                 :: "l"(p), "f"(v.x), "f"(v.y), "l"(pol) : "memory");
}
__device__ __forceinline__ void cp_async16(unsigned saddr, const void* gaddr) {
    asm volatile("cp.async.cg.shared.global [%0], [%1], 16;"
                 :: "r"(saddr), "l"(gaddr));
}
__device__ __forceinline__ void cp_commit() {
    asm volatile("cp.async.commit_group;");
}
__device__ __forceinline__ void cp_wait0() {
    asm volatile("cp.async.wait_group 0;");
}

// ---------------- CSR build (3 kernels) -------------------------------------
__global__ void k_count(const int* __restrict__ dst, int* cnt, int* bflag, int e) {
    int i = blockIdx.x * blockDim.x + threadIdx.x;
    if (i < NB) bflag[i] = 0;
    if (i < e) atomicAdd(&cnt[dst[i]], 1);
}

__global__ void k_scanlb(int* cnt, int* rowstart, int* cursor, float* dinv,
                         int* bagg, int* bpre, int* bflag, int e, int n) {
    __shared__ int sh[SEG];
    __shared__ int s_run;
    const int b = blockIdx.x;
    const int tid = threadIdx.x;
    const int i = b * SEG + tid;

    int v = (i < n) ? cnt[i] : 0;
    sh[tid] = v;
    __syncthreads();
#pragma unroll
    for (int o = 1; o < SEG; o <<= 1) {
        int t = (tid >= o) ? sh[tid - o] : 0;
        __syncthreads();
        sh[tid] += t;
        __syncthreads();
    }
    int excl = sh[tid] - v;
    int total = sh[SEG - 1];

    if (tid == 0) {
        if (b == 0) {
            bpre[0] = 0;
            bagg[0] = total;
            __threadfence();
            atomicExch(&bflag[0], 2);
            s_run = 0;
        } else {
            bagg[b] = total;
            __threadfence();
            atomicExch(&bflag[b], 1);
            int running = 0;
            int j = b - 1;
            while (j >= 0) {
                int f;
                do { f = atomicAdd(&bflag[j], 0); } while (f == 0);
                if (f == 2) { running += bpre[j] + bagg[j]; break; }
                running += bagg[j];
                --j;
            }
            bpre[b] = running;
            __threadfence();
            atomicExch(&bflag[b], 2);
            s_run = running;
        }
    }
    __syncthreads();
    int run = s_run;

    if (i < n) {
        int r = excl + run;
        rowstart[i] = r;
        cursor[i]   = r;
        dinv[i]     = rsqrtf((float)(v + 1));
        cnt[i]      = 0;
    }
    if (b == 0 && tid == 0) rowstart[n] = e;
}

__global__ void k_scatter(const int* __restrict__ src, const int* __restrict__ dst,
                          const float* __restrict__ dinv, int* cursor,
                          int* csr_src, float* csr_w, int e) {
    int i = blockIdx.x * blockDim.x + threadIdx.x;
    if (i >= e) return;
    int s = src[i], d = dst[i];
    int p = atomicAdd(&cursor[d], 1);
    csr_src[p] = s;
    csr_w[p]   = dinv[s] * dinv[d];
}

// ---------------------------------------------------------------------------
// fp32 fused gather (warp per dst node, unroll 4)
// ---------------------------------------------------------------------------
__global__ void k_gather(const float* __restrict__ feat,
                         const float* __restrict__ dinv,
                         const int* __restrict__ rowstart,
                         const int* __restrict__ csr_src,
                         const float* __restrict__ csr_w,
                         const float* __restrict__ bias,
                         const float* __restrict__ res,
                         float* __restrict__ out, int n) {
    int v = (blockIdx.x * blockDim.x + threadIdx.x) >> 5;
    int lane = threadIdx.x & 31;
    if (v >= n) return;

    const ULL polLast  = policy_evict_last();
    const ULL polFirst = policy_evict_first();

    int beg = rowstart[v];
    int end = rowstart[v + 1];
    float dv = dinv[v];
    float sl = dv * dv;
    const size_t lo = (size_t)(lane << 2);

    float4 acc = ld_hint_f4(feat + (size_t)v * 128 + lo, polLast);
    acc.x *= sl; acc.y *= sl; acc.z *= sl; acc.w *= sl;

    int i = beg;
    for (; i + 3 < end; i += 4) {
        int   s0 = csr_src[i],     s1 = csr_src[i + 1];
        int   s2 = csr_src[i + 2], s3 = csr_src[i + 3];
        float w0 = csr_w[i],       w1 = csr_w[i + 1];
        float w2 = csr_w[i + 2],   w3 = csr_w[i + 3];
        float4 x0 = ld_hint_f4(feat + (size_t)s0 * 128 + lo, polLast);
        float4 x1 = ld_hint_f4(feat + (size_t)s1 * 128 + lo, polLast);
        float4 x2 = ld_hint_f4(feat + (size_t)s2 * 128 + lo, polLast);
        float4 x3 = ld_hint_f4(feat + (size_t)s3 * 128 + lo, polLast);
        acc.x = fmaf(w0, x0.x, acc.x); acc.y = fmaf(w0, x0.y, acc.y);
        acc.z = fmaf(w0, x0.z, acc.z); acc.w = fmaf(w0, x0.w, acc.w);
        acc.x = fmaf(w1, x1.x, acc.x); acc.y = fmaf(w1, x1.y, acc.y);
        acc.z = fmaf(w1, x1.z, acc.z); acc.w = fmaf(w1, x1.w, acc.w);
        acc.x = fmaf(w2, x2.x, acc.x); acc.y = fmaf(w2, x2.y, acc.y);
        acc.z = fmaf(w2, x2.z, acc.z); acc.w = fmaf(w2, x2.w, acc.w);
        acc.x = fmaf(w3, x3.x, acc.x); acc.y = fmaf(w3, x3.y, acc.y);
        acc.z = fmaf(w3, x3.z, acc.z); acc.w = fmaf(w3, x3.w, acc.w);
    }
    for (; i < end; i++) {
        int   s0 = csr_src[i];
        float w0 = csr_w[i];
        float4 x0 = ld_hint_f4(feat + (size_t)s0 * 128 + lo, polLast);
        acc.x = fmaf(w0, x0.x, acc.x); acc.y = fmaf(w0, x0.y, acc.y);
        acc.z = fmaf(w0, x0.z, acc.z); acc.w = fmaf(w0, x0.w, acc.w);
    }

    float4 bb = ((const float4*)bias)[lane];
    acc.x = fmaxf(acc.x + bb.x, 0.f);
    acc.y = fmaxf(acc.y + bb.y, 0.f);
    acc.z = fmaxf(acc.z + bb.z, 0.f);
    acc.w = fmaxf(acc.w + bb.w, 0.f);
    if (res) {
        float4 rr = ld_hint_f4(res + (size_t)v * 128 + lo, polFirst);
        acc.x += rr.x; acc.y += rr.y; acc.z += rr.z; acc.w += rr.w;
    }
    st_hint_f4(out + (size_t)v * 128 + lo, acc, polFirst);
}

// ---------------------------------------------------------------------------
// tf32 MMA GEMM, double-buffered: C[M,128] = A[M,128] @ B[128,128]
// BM=64 BN=128 BK=32, 256 threads (8 warps: 2 over M x 4 over N, warp 32x32)
// A rounded-to-tf32 at smem store; B raw via cp.async, rounded at frag read
// ---------------------------------------------------------------------------
__global__ void __launch_bounds__(256)
k_gemm_tf32(const float* __restrict__ A,
            const float* __restrict__ B,
            float* __restrict__ Cm, int M) {
    __shared__ unsigned AsT[2][32][72];
    __shared__ unsigned Bs [2][32][136];

    const int tid  = threadIdx.x;
    const int lane = tid & 31;
    const int wid  = tid >> 5;
    const int warp_m = wid & 1;
    const int warp_n = wid >> 1;
    const int rowBase = blockIdx.x * 64;

    const int r = lane >> 2;
    const int t = lane & 3;

    const int am  = tid & 63;
    const int akq = tid >> 6;
    const int gr  = rowBase + am;

    float acc[2][4][4];
#pragma unroll
    for (int i = 0; i < 2; i++)
#pragma unroll
        for (int j = 0; j < 4; j++)
#pragma unroll
            for (int q = 0; q < 4; q++) acc[i][j][q] = 0.0f;

    float4 areg[2];

    // ---- prologue: tile 0
#pragma unroll
    for (int it = 0; it < 2; it++) {
        int kq = akq + it * 4;
        areg[it] = make_float4(0.f, 0.f, 0.f, 0.f);
        if (gr < M) areg[it] = *(const float4*)(A + (size_t)gr * 128 + kq * 4);
        AsT[0][kq * 4 + 0][am] = rn_tf32(areg[it].x);
        AsT[0][kq * 4 + 1][am] = rn_tf32(areg[it].y);
        AsT[0][kq * 4 + 2][am] = rn_tf32(areg[it].z);
        AsT[0][kq * 4 + 3][am] = rn_tf32(areg[it].w);
    }
#pragma unroll
    for (int it = 0; it < 4; it++) {
        int idx = tid + it * 256;
        int k   = idx >> 5;
        int n4  = (idx & 31) << 2;
        unsigned saddr = (unsigned)__cvta_generic_to_shared(&Bs[0][k][n4]);
        cp_async16(saddr, B + (size_t)k * 128 + n4);
    }
    cp_commit();
    cp_wait0();
    __syncthreads();

    for (int kt = 0; kt < 4; kt++) {
        const int cur = kt & 1;
        const int nxt = cur ^ 1;
        const int k1 = (kt + 1) * 32;

        if (kt < 3) {
#pragma unroll
            for (int it = 0; it < 2; it++) {
                int kq = akq + it * 4;
                areg[it] = make_float4(0.f, 0.f, 0.f, 0.f);
                if (gr < M) areg[it] = *(const float4*)(A + (size_t)gr * 128 + k1 + kq * 4);
            }
#pragma unroll
            for (int it = 0; it < 4; it++) {
                int idx = tid + it * 256;
                int k   = idx >> 5;
                int n4  = (idx & 31) << 2;
                unsigned saddr = (unsigned)__cvta_generic_to_shared(&Bs[nxt][k][n4]);
                cp_async16(saddr, B + (size_t)(k1 + k) * 128 + n4);
            }
            cp_commit();
        }

        // ---- compute on cur
#pragma unroll
        for (int ks = 0; ks < 4; ks++) {
            const int kb = ks * 8;
            unsigned a[2][4];
#pragma unroll
            for (int fm = 0; fm < 2; fm++) {
                int mb = warp_m * 32 + fm * 16;
                a[fm][0] = AsT[cur][kb + t    ][mb + r];
                a[fm][1] = AsT[cur][kb + t    ][mb + r + 8];
                a[fm][2] = AsT[cur][kb + t + 4][mb + r];
                a[fm][3] = AsT[cur][kb + t + 4][mb + r + 8];
            }
#pragma unroll
            for (int fn = 0; fn < 4; fn++) {
                int nb = warp_n * 32 + fn * 8;
                unsigned b0 = Bs[cur][kb + t    ][nb + r] + 0x1000u;  // RN to tf32
                unsigned b1 = Bs[cur][kb + t + 4][nb + r] + 0x1000u;
#pragma unroll
                for (int fm = 0; fm < 2; fm++) {
                    asm("mma.sync.aligned.m16n8k8.row.col.f32.tf32.tf32.f32 "
                        "{%0,%1,%2,%3}, {%4,%5,%6,%7}, {%8,%9}, {%0,%1,%2,%3};"
                        : "+f"(acc[fm][fn][0]), "+f"(acc[fm][fn][1]),
                          "+f"(acc[fm][fn][2]), "+f"(acc[fm][fn][3])
                        : "r"(a[fm][0]), "r"(a[fm][1]), "r"(a[fm][2]), "r"(a[fm][3]),
                          "r"(b0), "r"(b1));
                }
            }
        }

        if (kt < 3) {
#pragma unroll
            for (int it = 0; it < 2; it++) {
                int kq = akq + it * 4;
                AsT[nxt][kq * 4 + 0][am] = rn_tf32(areg[it].x);
                AsT[nxt][kq * 4 + 1][am] = rn_tf32(areg[it].y);
                AsT[nxt][kq * 4 + 2][am] = rn_tf32(areg[it].z);
                AsT[nxt][kq * 4 + 3][am] = rn_tf32(areg[it].w);
            }
            cp_wait0();
            __syncthreads();
        }
    }

    const ULL polLast = policy_evict_last();

#pragma unroll
    for (int fm = 0; fm < 2; fm++) {
        int r0 = rowBase + warp_m * 32 + fm * 16 + r;
        int r1 = r0 + 8;
#pragma unroll
        for (int fn = 0; fn < 4; fn++) {
            int col = warp_n * 32 + fn * 8 + 2 * t;
            if (r0 < M)
                st_hint_f2(Cm + (size_t)r0 * 128 + col,
                           make_float2(acc[fm][fn][0], acc[fm][fn][1]), polLast);
            if (r1 < M)
                st_hint_f2(Cm + (size_t)r1 * 128 + col,
                           make_float2(acc[fm][fn][2], acc[fm][fn][3]), polLast);
        }
    }
}

// ---------------------------------------------------------------------------
// classifier GEMM + fused log_softmax (packed f32x2)
// ---------------------------------------------------------------------------
__global__ void k_cls_gemm(const float* __restrict__ h,
                           const float* __restrict__ wl,
                           const float* __restrict__ bl,
                           float* __restrict__ out, int n) {
    __shared__ float AsT[16][258];
    __shared__ float Bsf[16 * C];
    __shared__ float sbl[C];

    const int tx = threadIdx.x & 7;
    const int ty = threadIdx.x >> 3;
    const int rowBase = blockIdx.x * 256;

    if (threadIdx.x < C) sbl[threadIdx.x] = bl[threadIdx.x];

    ULL acc[4][5];
#pragma unroll
    for (int i = 0; i < 4; i++)
#pragma unroll
        for (int j = 0; j < 5; j++) acc[i][j] = 0ull;

    const int gr = rowBase + threadIdx.x;

    for (int k0 = 0; k0 < 128; k0 += 16) {
#pragma unroll
        for (int i = 0; i < 4; i++) {
            float4 v = make_float4(0.f, 0.f, 0.f, 0.f);
            if (gr < n) v = *(const float4*)(h + (size_t)gr * 128 + k0 + i * 4);
            AsT[i * 4 + 0][threadIdx.x] = v.x;
            AsT[i * 4 + 1][threadIdx.x] = v.y;
            AsT[i * 4 + 2][threadIdx.x] = v.z;
            AsT[i * 4 + 3][threadIdx.x] = v.w;
        }
        for (int i = threadIdx.x; i < 16 * C; i += 256)
            Bsf[i] = wl[k0 * C + i];
        __syncthreads();

#pragma unroll 4
        for (int kk = 0; kk < 16; kk++) {
            ULL a0 = *(const ULL*)&AsT[kk][ty * 8 + 0];
            ULL a1 = *(const ULL*)&AsT[kk][ty * 8 + 2];
            ULL a2 = *(const ULL*)&AsT[kk][ty * 8 + 4];
            ULL a3 = *(const ULL*)&AsT[kk][ty * 8 + 6];
            const float* bp = &Bsf[kk * C + tx * 5];
            ULL b0 = fdup(bp[0]), b1 = fdup(bp[1]), b2 = fdup(bp[2]);
            ULL b3 = fdup(bp[3]), b4 = fdup(bp[4]);
#define CLS_ROW(i, ai) \
            acc[i][0] = ffma2(ai, b0, acc[i][0]); \
            acc[i][1] = ffma2(ai, b1, acc[i][1]); \
            acc[i][2] = ffma2(ai, b2, acc[i][2]); \
            acc[i][3] = ffma2(ai, b3, acc[i][3]); \
            acc[i][4] = ffma2(ai, b4, acc[i][4]);
            CLS_ROW(0, a0) CLS_ROW(1, a1) CLS_ROW(2, a2) CLS_ROW(3, a3)
#undef CLS_ROW
        }
        __syncthreads();
    }

    const float bb0 = sbl[tx * 5 + 0], bb1 = sbl[tx * 5 + 1], bb2 = sbl[tx * 5 + 2];
    const float bb3 = sbl[tx * 5 + 3], bb4 = sbl[tx * 5 + 4];

#pragma unroll
    for (int i = 0; i < 4; i++) {
#pragma unroll
        for (int half = 0; half < 2; half++) {
            int r0 = rowBase + ty * 8 + 2 * i + half;
            float2 q0 = *(float2*)&acc[i][0];
            float2 q1 = *(float2*)&acc[i][1];
            float2 q2 = *(float2*)&acc[i][2];
            float2 q3 = *(float2*)&acc[i][3];
            float2 q4 = *(float2*)&acc[i][4];
            float l0 = (half ? q0.y : q0.x) + bb0;
            float l1 = (half ? q1.y : q1.x) + bb1;
            float l2 = (half ? q2.y : q2.x) + bb2;
            float l3 = (half ? q3.y : q3.x) + bb3;
            float l4 = (half ? q4.y : q4.x) + bb4;

            float m = fmaxf(fmaxf(fmaxf(l0, l1), fmaxf(l2, l3)), l4);
            m = fmaxf(m, __shfl_xor_sync(0xffffffffu, m, 1));
            m = fmaxf(m, __shfl_xor_sync(0xffffffffu, m, 2));
            m = fmaxf(m, __shfl_xor_sync(0xffffffffu, m, 4));
            float se = __expf(l0 - m) + __expf(l1 - m) + __expf(l2 - m)
                     + __expf(l3 - m) + __expf(l4 - m);
            se += __shfl_xor_sync(0xffffffffu, se, 1);
            se += __shfl_xor_sync(0xffffffffu, se, 2);
            se += __shfl_xor_sync(0xffffffffu, se, 4);
            float lse = __logf(se) + m;

            if (r0 < n) {
                float* op = out + (size_t)r0 * C + tx * 5;
                op[0] = l0 - lse; op[1] = l1 - lse; op[2] = l2 - lse;
                op[3] = l3 - lse; op[4] = l4 - lse;
            }
        }
    }
}

// ---------------------------------------------------------------------------
// launch — CSR build forked onto stream 2, overlapping GEMM0
// ---------------------------------------------------------------------------
extern "C" void kernel_launch(void* const* d_in, const int* in_sizes, int n_in,
                              void* d_out, int out_size) {
    const float* x   = (const float*)d_in[0];
    const int*   ei  = (const int*)d_in[1];
    const float* w0  = (const float*)d_in[2];
    const float* b0  = (const float*)d_in[3];
    const float* w1  = (const float*)d_in[4];
    const float* b1  = (const float*)d_in[5];
    const float* wl  = (const float*)d_in[6];
    const float* bl  = (const float*)d_in[7];
    float* out = (float*)d_out;

    const int n = in_sizes[0] / H;
    const int e = in_sizes[1] / 2;
    const int* src = ei;
    const int* dst = ei + e;

    float *dinv, *lin, *agg, *h0, *csr_w;
    int *cnt, *rowstart, *cursor, *csr_src, *bagg, *bpre, *bflag;
    cudaGetSymbolAddress((void**)&dinv,     g_dinv);
    cudaGetSymbolAddress((void**)&cnt,      g_cnt);
    cudaGetSymbolAddress((void**)&rowstart, g_rowstart);
    cudaGetSymbolAddress((void**)&cursor,   g_cursor);
    cudaGetSymbolAddress((void**)&bagg,     g_bagg);
    cudaGetSymbolAddress((void**)&bpre,     g_bpre);
    cudaGetSymbolAddress((void**)&bflag,    g_bflag);
    cudaGetSymbolAddress((void**)&csr_src,  g_csr_src);
    cudaGetSymbolAddress((void**)&csr_w,    g_csr_w);
    cudaGetSymbolAddress((void**)&lin,      g_lin);
    cudaGetSymbolAddress((void**)&agg,      g_agg);
    cudaGetSymbolAddress((void**)&h0,       g_h0);

    static cudaStream_t s2 = nullptr;
    static cudaEvent_t evFork = nullptr, evJoin = nullptr;
    if (!s2) {
        cudaStreamCreateWithFlags(&s2, cudaStreamNonBlocking);
        cudaEventCreateWithFlags(&evFork, cudaEventDisableTiming);
        cudaEventCreateWithFlags(&evJoin, cudaEventDisableTiming);
    }

    const int TB = 256;
    const int nb = (n + SEG - 1) / SEG;
    const int gemmBlocks   = (n + 63) / 64;
    const int gatherBlocks = (n * 32 + TB - 1) / TB;

    // fork: CSR build on s2, GEMM0 on main
    cudaEventRecord(evFork, 0);
    cudaStreamWaitEvent(s2, evFork, 0);

    k_count  <<<(e + TB - 1) / TB, TB, 0, s2>>>(dst, cnt, bflag, e);
    k_scanlb <<<nb, SEG, 0, s2>>>(cnt, rowstart, cursor, dinv, bagg, bpre, bflag, e, n);
    k_scatter<<<(e + TB - 1) / TB, TB, 0, s2>>>(src, dst, dinv, cursor, csr_src, csr_w, e);
    cudaEventRecord(evJoin, s2);

    k_gemm_tf32<<<gemmBlocks, TB>>>(x, w0, lin, n);

    cudaStreamWaitEvent(0, evJoin, 0);

    k_gather<<<gatherBlocks, TB>>>(lin, dinv, rowstart, csr_src, csr_w,
                                   b0, nullptr, h0, n);
    k_gemm_tf32<<<gemmBlocks, TB>>>(h0, w1, lin, n);
    k_gather<<<gatherBlocks, TB>>>(lin, dinv, rowstart, csr_src, csr_w,
                                   b1, h0, agg, n);
    k_cls_gemm<<<(n + 255) / 256, TB>>>(agg, wl, bl, out, n);
}